// round 2
// baseline (speedup 1.0000x reference)
#include <cuda_runtime.h>

#define NSIDE 128
#define NPIX (12*NSIDE*NSIDE)   /* 196608 */
#define B 8
#define CIN 16
#define COUT 32
#define BC (B*CIN)              /* 128 */
#define TILE_P 32
#define VSTRIDE (9*CIN*B + 4)   /* 1156 floats: per-pixel tile + pad to avoid lp bank aliasing */
#define SMEM_BYTES ((4608 + TILE_P*VSTRIDE)*4 + 288*4)   /* 167552 */

// scratch: transposed, zero-padded x  (pixel-major: xt[idx][c*8+b])
__device__ float g_xt[(NPIX + 1) * BC];

// ---------------------------------------------------------------------------
// Kernel A: transpose x [B][CIN][NPIX] -> xt [NPIX+1][c*8+b], row NPIX = zeros
// ---------------------------------------------------------------------------
__global__ void transpose_kernel(const float* __restrict__ x) {
    __shared__ float tile[BC * 33];   // stride 33 -> conflict-free both phases
    const int tid  = threadIdx.x;
    const int idx0 = blockIdx.x * 32;

    // load: coalesced 128B rows of x; store permuted (cc = c*8+b)
    #pragma unroll
    for (int i = tid; i < BC * 32; i += 256) {
        int r  = i >> 5;            // r = b*16 + c
        int j  = i & 31;
        int cc = (r & 15) * 8 + (r >> 4);
        tile[cc * 33 + j] = x[r * NPIX + idx0 + j];
    }
    __syncthreads();
    // store: coalesced 512B rows of xt
    #pragma unroll
    for (int i = tid; i < BC * 32; i += 256) {
        int j  = i >> 7;
        int cc = i & 127;
        g_xt[(idx0 + j) * BC + cc] = tile[cc * 33 + j];
    }
    if (blockIdx.x == 0 && tid < BC) g_xt[NPIX * BC + tid] = 0.0f;
}

// ---------------------------------------------------------------------------
// Packed f32x2 helpers (Blackwell FFMA2 — only reachable via PTX)
// ---------------------------------------------------------------------------
__device__ __forceinline__ unsigned long long ffma2(unsigned long long a,
                                                    unsigned long long b,
                                                    unsigned long long c) {
    unsigned long long d;
    asm("fma.rn.f32x2 %0, %1, %2, %3;" : "=l"(d) : "l"(a), "l"(b), "l"(c));
    return d;
}
__device__ __forceinline__ unsigned long long pack2(float x) {
    unsigned long long r;
    unsigned u = __float_as_uint(x);
    asm("mov.b64 %0, {%1, %1};" : "=l"(r) : "r"(u));
    return r;
}

// ---------------------------------------------------------------------------
// Kernel B: per-tile gather + register-blocked conv
//   block = 256 threads = 32 pixels x 8 o-groups; thread tile = 8b x 4o
// ---------------------------------------------------------------------------
__global__ void __launch_bounds__(256, 1) conv_kernel(
    const float* __restrict__ weight,   // [COUT][CIN][9]
    const float* __restrict__ bias,     // [COUT]
    const int*   __restrict__ neigh,    // [NPIX][9]
    float*       __restrict__ out)      // [B][COUT][NPIX]
{
    extern __shared__ char smem[];
    float* wS = (float*)smem;                      // [9][16][32]  = 4608 f
    float* vS = wS + 4608;                         // [32][VSTRIDE]
    int*   nS = (int*)(vS + TILE_P * VSTRIDE);     // [288]
    float* oS = vS;                                // reused after compute

    const int tid = threadIdx.x;
    const int p0  = blockIdx.x * TILE_P;

    // stage weights as wS[k][c][o]
    for (int i = tid; i < 4608; i += 256) {
        int k = i >> 9, rem = i & 511, c = rem >> 5, o = rem & 31;
        wS[i] = weight[o * 144 + c * 9 + k];
    }
    // FIX (R1): 288 entries, 256 threads -> must stride, not predicate
    for (int i = tid; i < TILE_P * 9; i += 256) nS[i] = neigh[p0 * 9 + i];
    __syncthreads();

    // gather: one neighbour row = 512B contiguous (all b,c for that pixel)
    const float4* xt4 = (const float4*)g_xt;
    for (int i = tid; i < TILE_P * 9 * 32; i += 256) {
        int row = i >> 5, seg = i & 31;
        int lp  = row / 9, k = row - lp * 9;
        int idx = nS[row];
        float4 v = xt4[idx * 32 + seg];
        *(float4*)(vS + lp * VSTRIDE + k * 128 + seg * 4) = v;
    }
    __syncthreads();

    // compute: thread (lp, og) -> pixel p0+lp, outputs og*4..og*4+3, all 8 b
    const int lp = tid >> 3;
    const int og = tid & 7;

    unsigned long long acc[4][4];
    #pragma unroll
    for (int j = 0; j < 4; j++)
        #pragma unroll
        for (int i = 0; i < 4; i++) acc[j][i] = 0ULL;

    const ulonglong2* v2 = (const ulonglong2*)(vS + lp * VSTRIDE);
    const float4*     w4 = (const float4*)wS;

    for (int k = 0; k < 9; k++) {
        #pragma unroll
        for (int c = 0; c < CIN; c++) {
            const int t = k * CIN + c;
            ulonglong2 va = v2[t * 2 + 0];   // (b0,b1),(b2,b3)
            ulonglong2 vb = v2[t * 2 + 1];   // (b4,b5),(b6,b7)
            float4 w = w4[t * 8 + og];
            unsigned long long wp0 = pack2(w.x), wp1 = pack2(w.y),
                               wp2 = pack2(w.z), wp3 = pack2(w.w);
            acc[0][0] = ffma2(va.x, wp0, acc[0][0]);
            acc[0][1] = ffma2(va.x, wp1, acc[0][1]);
            acc[0][2] = ffma2(va.x, wp2, acc[0][2]);
            acc[0][3] = ffma2(va.x, wp3, acc[0][3]);
            acc[1][0] = ffma2(va.y, wp0, acc[1][0]);
            acc[1][1] = ffma2(va.y, wp1, acc[1][1]);
            acc[1][2] = ffma2(va.y, wp2, acc[1][2]);
            acc[1][3] = ffma2(va.y, wp3, acc[1][3]);
            acc[2][0] = ffma2(vb.x, wp0, acc[2][0]);
            acc[2][1] = ffma2(vb.x, wp1, acc[2][1]);
            acc[2][2] = ffma2(vb.x, wp2, acc[2][2]);
            acc[2][3] = ffma2(vb.x, wp3, acc[2][3]);
            acc[3][0] = ffma2(vb.y, wp0, acc[3][0]);
            acc[3][1] = ffma2(vb.y, wp1, acc[3][1]);
            acc[3][2] = ffma2(vb.y, wp2, acc[3][2]);
            acc[3][3] = ffma2(vb.y, wp3, acc[3][3]);
        }
    }
    __syncthreads();   // all vS reads done before oS overwrite

    // epilogue: bias + stage to smem for coalesced global writes
    float4 bs = ((const float4*)bias)[og];
    float bi[4] = {bs.x, bs.y, bs.z, bs.w};
    #pragma unroll
    for (int j = 0; j < 4; j++) {
        #pragma unroll
        for (int i = 0; i < 4; i++) {
            float lo = __uint_as_float((unsigned)(acc[j][i] & 0xffffffffu));
            float hi = __uint_as_float((unsigned)(acc[j][i] >> 32));
            int o = og * 4 + i;
            oS[((2 * j)     * COUT + o) * 33 + lp] = lo + bi[i];
            oS[((2 * j + 1) * COUT + o) * 33 + lp] = hi + bi[i];
        }
    }
    __syncthreads();

    for (int i = tid; i < B * COUT * TILE_P; i += 256) {
        int row = i >> 5, col = i & 31;     // row = b*32+o
        out[row * NPIX + p0 + col] = oS[row * 33 + col];
    }
}

// ---------------------------------------------------------------------------
extern "C" void kernel_launch(void* const* d_in, const int* in_sizes, int n_in,
                              void* d_out, int out_size) {
    const float* x      = (const float*)d_in[0];
    const float* weight = (const float*)d_in[1];
    const float* bias   = (const float*)d_in[2];
    const int*   neigh  = (const int*)d_in[3];
    float*       out    = (float*)d_out;

    cudaFuncSetAttribute(conv_kernel,
                         cudaFuncAttributeMaxDynamicSharedMemorySize,
                         SMEM_BYTES);

    transpose_kernel<<<NPIX / 32, 256>>>(x);
    conv_kernel<<<NPIX / TILE_P, 256, SMEM_BYTES>>>(weight, bias, neigh, out);
}

// round 3
// speedup vs baseline: 1.7557x; 1.7557x over previous
#include <cuda_runtime.h>
#include <cstdint>

#define NSIDE 128
#define NPIX (12*NSIDE*NSIDE)   /* 196608 */
#define B 8
#define CIN 16
#define COUT 32
#define BC (B*CIN)              /* 128 */
#define TILE_P 16
#define NROWS (TILE_P*9)        /* 144 */
#define VSTRIDE (9*CIN*B + 4)   /* 1156 floats; +4 keeps 16B align & breaks bank aliasing */
#define WS_FLOATS 4608
#define SMEM_BYTES ((WS_FLOATS + TILE_P*VSTRIDE)*4 + NROWS*4)   /* 92992 */

// scratch: transposed, zero-padded x  (pixel-major: xt[idx][c*8+b])
__device__ float g_xt[(NPIX + 1) * BC];

// ---------------------------------------------------------------------------
// Kernel A: transpose x [B][CIN][NPIX] -> xt [NPIX+1][c*8+b], row NPIX = zeros
// ---------------------------------------------------------------------------
__global__ void transpose_kernel(const float* __restrict__ x) {
    __shared__ float tile[BC * 33];
    const int tid  = threadIdx.x;
    const int idx0 = blockIdx.x * 32;

    #pragma unroll
    for (int i = tid; i < BC * 32; i += 256) {
        int r  = i >> 5;            // r = b*16 + c
        int j  = i & 31;
        int cc = (r & 15) * 8 + (r >> 4);
        tile[cc * 33 + j] = x[r * NPIX + idx0 + j];
    }
    __syncthreads();
    #pragma unroll
    for (int i = tid; i < BC * 32; i += 256) {
        int j  = i >> 7;
        int cc = i & 127;
        g_xt[(idx0 + j) * BC + cc] = tile[cc * 33 + j];
    }
    if (blockIdx.x == 0 && tid < BC) g_xt[NPIX * BC + tid] = 0.0f;
}

// ---------------------------------------------------------------------------
// Packed f32x2 + cp.async helpers
// ---------------------------------------------------------------------------
__device__ __forceinline__ unsigned long long ffma2(unsigned long long a,
                                                    unsigned long long b,
                                                    unsigned long long c) {
    unsigned long long d;
    asm("fma.rn.f32x2 %0, %1, %2, %3;" : "=l"(d) : "l"(a), "l"(b), "l"(c));
    return d;
}
__device__ __forceinline__ unsigned long long pack2(float x) {
    unsigned long long r;
    unsigned u = __float_as_uint(x);
    asm("mov.b64 %0, {%1, %1};" : "=l"(r) : "r"(u));
    return r;
}
__device__ __forceinline__ void cp_async16(uint32_t dst_smem, const void* src) {
    asm volatile("cp.async.cg.shared.global [%0], [%1], 16;\n"
                 :: "r"(dst_smem), "l"(src));
}

// ---------------------------------------------------------------------------
// Kernel B: 16-pixel tiles, 2 CTAs/SM; thread tile = 8b x 2o
// ---------------------------------------------------------------------------
__global__ void __launch_bounds__(256, 2) conv_kernel(
    const float* __restrict__ weight,   // [COUT][CIN][9]
    const float* __restrict__ bias,     // [COUT]
    const int*   __restrict__ neigh,    // [NPIX][9]
    float*       __restrict__ out)      // [B][COUT][NPIX]
{
    extern __shared__ char smem[];
    float* wS = (float*)smem;                      // [9][16][32] = 4608 f
    float* vS = wS + WS_FLOATS;                    // [16][VSTRIDE]
    int*   nS = (int*)(vS + TILE_P * VSTRIDE);     // [144]
    float* oS = vS;                                // reused after compute

    const int tid = threadIdx.x;
    const int p0  = blockIdx.x * TILE_P;

    // stage weights as wS[k][c][o]
    for (int i = tid; i < WS_FLOATS; i += 256) {
        int k = i >> 9, rem = i & 511, c = rem >> 5, o = rem & 31;
        wS[i] = weight[o * 144 + c * 9 + k];
    }
    if (tid < NROWS) nS[tid] = neigh[p0 * 9 + tid];   // 144 < 256: predicate OK
    __syncthreads();

    // gather via cp.async: one neighbour row = 512B contiguous
    const uint32_t vS_u32 = (uint32_t)__cvta_generic_to_shared(vS);
    #pragma unroll
    for (int i = tid; i < NROWS * 32; i += 256) {     // 18 iters
        int row = i >> 5, seg = i & 31;
        int lp  = row / 9, k = row - lp * 9;
        int idx = nS[row];
        uint32_t dst = vS_u32 + (lp * VSTRIDE + k * 128 + seg * 4) * 4;
        cp_async16(dst, g_xt + (size_t)idx * BC + seg * 4);
    }
    asm volatile("cp.async.commit_group;\n" ::: "memory");
    asm volatile("cp.async.wait_group 0;\n" ::: "memory");
    __syncthreads();

    // compute: thread (lp, og) -> pixel p0+lp, outputs og*2, og*2+1, all 8 b
    const int lp = tid >> 4;
    const int og = tid & 15;

    unsigned long long acc[4][2];
    #pragma unroll
    for (int j = 0; j < 4; j++) { acc[j][0] = 0ULL; acc[j][1] = 0ULL; }

    const ulonglong2* v2 = (const ulonglong2*)(vS + lp * VSTRIDE);

    for (int k = 0; k < 9; k++) {
        #pragma unroll
        for (int c = 0; c < CIN; c++) {
            const int t = k * CIN + c;
            ulonglong2 va = v2[t * 2 + 0];   // (b0,b1),(b2,b3)
            ulonglong2 vb = v2[t * 2 + 1];   // (b4,b5),(b6,b7)
            float2 w = *(const float2*)(wS + t * 32 + og * 2);
            unsigned long long wp0 = pack2(w.x), wp1 = pack2(w.y);
            acc[0][0] = ffma2(va.x, wp0, acc[0][0]);
            acc[0][1] = ffma2(va.x, wp1, acc[0][1]);
            acc[1][0] = ffma2(va.y, wp0, acc[1][0]);
            acc[1][1] = ffma2(va.y, wp1, acc[1][1]);
            acc[2][0] = ffma2(vb.x, wp0, acc[2][0]);
            acc[2][1] = ffma2(vb.x, wp1, acc[2][1]);
            acc[3][0] = ffma2(vb.y, wp0, acc[3][0]);
            acc[3][1] = ffma2(vb.y, wp1, acc[3][1]);
        }
    }
    __syncthreads();   // all vS reads done before oS overwrite

    // epilogue: bias + stage to smem, then coalesced global writes
    float2 bs = ((const float2*)bias)[og];
    #pragma unroll
    for (int j = 0; j < 4; j++) {
        #pragma unroll
        for (int i = 0; i < 2; i++) {
            float bi = (i == 0) ? bs.x : bs.y;
            float lo = __uint_as_float((unsigned)(acc[j][i] & 0xffffffffu));
            float hi = __uint_as_float((unsigned)(acc[j][i] >> 32));
            int o = og * 2 + i;
            oS[((2 * j)     * COUT + o) * (TILE_P + 1) + lp] = lo + bi;
            oS[((2 * j + 1) * COUT + o) * (TILE_P + 1) + lp] = hi + bi;
        }
    }
    __syncthreads();

    #pragma unroll
    for (int i = tid; i < B * COUT * TILE_P; i += 256) {   // 4096
        int row = i >> 4, col = i & 15;     // row = b*32+o
        out[row * NPIX + p0 + col] = oS[row * (TILE_P + 1) + col];
    }
}

// ---------------------------------------------------------------------------
extern "C" void kernel_launch(void* const* d_in, const int* in_sizes, int n_in,
                              void* d_out, int out_size) {
    const float* x      = (const float*)d_in[0];
    const float* weight = (const float*)d_in[1];
    const float* bias   = (const float*)d_in[2];
    const int*   neigh  = (const int*)d_in[3];
    float*       out    = (float*)d_out;

    cudaFuncSetAttribute(conv_kernel,
                         cudaFuncAttributeMaxDynamicSharedMemorySize,
                         SMEM_BYTES);

    transpose_kernel<<<NPIX / 32, 256>>>(x);
    conv_kernel<<<NPIX / TILE_P, 256, SMEM_BYTES>>>(weight, bias, neigh, out);
}

// round 4
// speedup vs baseline: 2.4135x; 1.3747x over previous
#include <cuda_runtime.h>
#include <cstdint>

#define NSIDE 128
#define NPIX (12*NSIDE*NSIDE)   /* 196608 */
#define B 8
#define CIN 16
#define COUT 32
#define BC (B*CIN)              /* 128 */
#define TILE_P 32
#define CSTRIDE 132             /* 128 floats per pixel-chunk row + 4 pad */
#define WS_FLOATS 4608
/* smem: weights + 2 chunk buffers + neigh table */
#define VB_FLOATS (2*TILE_P*CSTRIDE)          /* 8448 */
#define SMEM_BYTES ((WS_FLOATS + VB_FLOATS)*4 + TILE_P*9*4)   /* 53376 */

// scratch: transposed, zero-padded x  (pixel-major: xt[idx][c*8+b])
__device__ float g_xt[(NPIX + 1) * BC];

// ---------------------------------------------------------------------------
// Kernel A: transpose x [B][CIN][NPIX] -> xt [NPIX+1][c*8+b], row NPIX = zeros
// ---------------------------------------------------------------------------
__global__ void transpose_kernel(const float* __restrict__ x) {
    __shared__ float tile[BC * 33];
    const int tid  = threadIdx.x;
    const int idx0 = blockIdx.x * 32;

    #pragma unroll
    for (int i = tid; i < BC * 32; i += 256) {
        int r  = i >> 5;            // r = b*16 + c
        int j  = i & 31;
        int cc = (r & 15) * 8 + (r >> 4);
        tile[cc * 33 + j] = x[r * NPIX + idx0 + j];
    }
    __syncthreads();
    #pragma unroll
    for (int i = tid; i < BC * 32; i += 256) {
        int j  = i >> 7;
        int cc = i & 127;
        g_xt[(idx0 + j) * BC + cc] = tile[cc * 33 + j];
    }
    if (blockIdx.x == 0 && tid < BC) g_xt[NPIX * BC + tid] = 0.0f;
}

// ---------------------------------------------------------------------------
// Packed f32x2 + cp.async helpers
// ---------------------------------------------------------------------------
__device__ __forceinline__ unsigned long long ffma2(unsigned long long a,
                                                    unsigned long long b,
                                                    unsigned long long c) {
    unsigned long long d;
    asm("fma.rn.f32x2 %0, %1, %2, %3;" : "=l"(d) : "l"(a), "l"(b), "l"(c));
    return d;
}
__device__ __forceinline__ unsigned long long pack2(float x) {
    unsigned long long r;
    unsigned u = __float_as_uint(x);
    asm("mov.b64 %0, {%1, %1};" : "=l"(r) : "r"(u));
    return r;
}
__device__ __forceinline__ void cp_async16(uint32_t dst_smem, const void* src) {
    asm volatile("cp.async.cg.shared.global [%0], [%1], 16;\n"
                 :: "r"(dst_smem), "l"(src));
}

// ---------------------------------------------------------------------------
// Kernel B: 32-pixel tiles, k-streamed double-buffered gather, 2 CTAs/SM
//   thread tile = 8b x 4o  (256 thr = 32 lp x 8 og)
// ---------------------------------------------------------------------------
__global__ void __launch_bounds__(256, 2) conv_kernel(
    const float* __restrict__ weight,   // [COUT][CIN][9]
    const float* __restrict__ bias,     // [COUT]
    const int*   __restrict__ neigh,    // [NPIX][9]
    float*       __restrict__ out)      // [B][COUT][NPIX]
{
    extern __shared__ char smem[];
    float* wS = (float*)smem;                      // [9][16][32] = 4608 f
    float* vB = wS + WS_FLOATS;                    // [2][32][CSTRIDE]
    int*   nS = (int*)(vB + VB_FLOATS);            // [288]
    float* oS = vB;                                // reused after compute

    const int tid = threadIdx.x;
    const int p0  = blockIdx.x * TILE_P;

    // stage weights as wS[k][c][o]
    for (int i = tid; i < WS_FLOATS; i += 256) {
        int k = i >> 9, rem = i & 511, c = rem >> 5, o = rem & 31;
        wS[i] = weight[o * 144 + c * 9 + k];
    }
    for (int i = tid; i < TILE_P * 9; i += 256) nS[i] = neigh[p0 * 9 + i];
    __syncthreads();

    const uint32_t vB_u32 = (uint32_t)__cvta_generic_to_shared(vB);

    // chunk loader: one k-slice = 32 pixel rows x 512B -> 4 cp.async16 / thread
    auto load_chunk = [&](int k, int buf) {
        #pragma unroll
        for (int j = 0; j < 4; j++) {
            int i   = tid + j * 256;           // 0..1023
            int lp  = i >> 5, seg = i & 31;
            int idx = nS[lp * 9 + k];
            uint32_t dst = vB_u32 + (buf * TILE_P * CSTRIDE + lp * CSTRIDE + seg * 4) * 4;
            cp_async16(dst, g_xt + (size_t)idx * BC + seg * 4);
        }
        asm volatile("cp.async.commit_group;\n" ::: "memory");
    };

    load_chunk(0, 0);

    // compute mapping: thread (lp, og) -> pixel p0+lp, outputs og*4..og*4+3
    const int lp = tid >> 3;
    const int og = tid & 7;

    unsigned long long acc[4][4];
    #pragma unroll
    for (int j = 0; j < 4; j++)
        #pragma unroll
        for (int i = 0; i < 4; i++) acc[j][i] = 0ULL;

    const float4* w4 = (const float4*)wS;

    for (int k = 0; k < 9; k++) {
        if (k + 1 < 9) load_chunk(k + 1, (k + 1) & 1);
        if (k + 1 < 9) asm volatile("cp.async.wait_group 1;\n" ::: "memory");
        else           asm volatile("cp.async.wait_group 0;\n" ::: "memory");
        __syncthreads();

        const ulonglong2* v2 =
            (const ulonglong2*)(vB + ((k & 1) * TILE_P + lp) * CSTRIDE);

        #pragma unroll
        for (int c = 0; c < CIN; c++) {
            const int t = k * CIN + c;
            ulonglong2 va = v2[c * 2 + 0];   // (b0,b1),(b2,b3)
            ulonglong2 vb = v2[c * 2 + 1];   // (b4,b5),(b6,b7)
            float4 w = w4[t * 8 + og];
            unsigned long long wp0 = pack2(w.x), wp1 = pack2(w.y),
                               wp2 = pack2(w.z), wp3 = pack2(w.w);
            acc[0][0] = ffma2(va.x, wp0, acc[0][0]);
            acc[0][1] = ffma2(va.x, wp1, acc[0][1]);
            acc[0][2] = ffma2(va.x, wp2, acc[0][2]);
            acc[0][3] = ffma2(va.x, wp3, acc[0][3]);
            acc[1][0] = ffma2(va.y, wp0, acc[1][0]);
            acc[1][1] = ffma2(va.y, wp1, acc[1][1]);
            acc[1][2] = ffma2(va.y, wp2, acc[1][2]);
            acc[1][3] = ffma2(va.y, wp3, acc[1][3]);
            acc[2][0] = ffma2(vb.x, wp0, acc[2][0]);
            acc[2][1] = ffma2(vb.x, wp1, acc[2][1]);
            acc[2][2] = ffma2(vb.x, wp2, acc[2][2]);
            acc[2][3] = ffma2(vb.x, wp3, acc[2][3]);
            acc[3][0] = ffma2(vb.y, wp0, acc[3][0]);
            acc[3][1] = ffma2(vb.y, wp1, acc[3][1]);
            acc[3][2] = ffma2(vb.y, wp2, acc[3][2]);
            acc[3][3] = ffma2(vb.y, wp3, acc[3][3]);
        }
        __syncthreads();   // reads of buf (k&1) done before k+2 overwrites it
    }

    // epilogue: bias + stage to smem for coalesced global writes
    float4 bs = ((const float4*)bias)[og];
    float bi[4] = {bs.x, bs.y, bs.z, bs.w};
    #pragma unroll
    for (int j = 0; j < 4; j++) {
        #pragma unroll
        for (int i = 0; i < 4; i++) {
            float lo = __uint_as_float((unsigned)(acc[j][i] & 0xffffffffu));
            float hi = __uint_as_float((unsigned)(acc[j][i] >> 32));
            int o = og * 4 + i;
            oS[((2 * j)     * COUT + o) * (TILE_P + 1) + lp] = lo + bi[i];
            oS[((2 * j + 1) * COUT + o) * (TILE_P + 1) + lp] = hi + bi[i];
        }
    }
    __syncthreads();

    #pragma unroll
    for (int i = tid; i < B * COUT * TILE_P; i += 256) {   // 8192
        int row = i >> 5, col = i & 31;     // row = b*32+o
        out[row * NPIX + p0 + col] = oS[row * (TILE_P + 1) + col];
    }
}

// ---------------------------------------------------------------------------
extern "C" void kernel_launch(void* const* d_in, const int* in_sizes, int n_in,
                              void* d_out, int out_size) {
    const float* x      = (const float*)d_in[0];
    const float* weight = (const float*)d_in[1];
    const float* bias   = (const float*)d_in[2];
    const int*   neigh  = (const int*)d_in[3];
    float*       out    = (float*)d_out;

    cudaFuncSetAttribute(conv_kernel,
                         cudaFuncAttributeMaxDynamicSharedMemorySize,
                         SMEM_BYTES);

    transpose_kernel<<<NPIX / 32, 256>>>(x);
    conv_kernel<<<NPIX / TILE_P, 256, SMEM_BYTES>>>(weight, bias, neigh, out);
}